// round 2
// baseline (speedup 1.0000x reference)
#include <cuda_runtime.h>

// Problem constants
#define NB   4
#define HH   224
#define WW   224
#define CIN  256
#define FOUT 256
#define BC   16     // blocks per side
#define OBS  14     // output block size
#define CCH  8      // C chunk per smem stage
#define FT   64     // F per CTA

// Block activity gates (computed by kernel 1, read by kernel 2)
__device__ float g_active[NB * BC * BC];

// ---------------------------------------------------------------------------
// packed fp32x2 helpers (Blackwell FFMA2 path)
// ---------------------------------------------------------------------------
__device__ __forceinline__ unsigned long long pack2(float a, float b) {
    unsigned long long r;
    asm("mov.b64 %0, {%1, %2};" : "=l"(r) : "f"(a), "f"(b));
    return r;
}
__device__ __forceinline__ void fma2(unsigned long long& d, unsigned long long a,
                                     unsigned long long b) {
    asm("fma.rn.f32x2 %0, %1, %2, %0;" : "+l"(d) : "l"(a), "l"(b));
}
__device__ __forceinline__ float2 unpack2(unsigned long long v) {
    float2 r;
    asm("mov.b64 {%0, %1}, %2;" : "=f"(r.x), "=f"(r.y) : "l"(v));
    return r;
}

// ---------------------------------------------------------------------------
// Kernel 1: block gates.  active[n,bi,bj] = mean(16x16 padded mask win) > 0.5
// ---------------------------------------------------------------------------
__global__ void active_kernel(const float* __restrict__ mask) {
    int idx = blockIdx.x * blockDim.x + threadIdx.x;
    if (idx >= NB * BC * BC) return;
    int bj = idx & 15;
    int bi = (idx >> 4) & 15;
    int n  = idx >> 8;
    int y0 = bi * OBS - 1;
    int x0 = bj * OBS - 1;
    float s = 0.0f;
    for (int i = 0; i < 16; ++i) {
        int y = y0 + i;
        if ((unsigned)y >= (unsigned)HH) continue;
        const float* row = mask + (n * HH + y) * WW;
        for (int j = 0; j < 16; ++j) {
            int x = x0 + j;
            if ((unsigned)x < (unsigned)WW) s += row[x];
        }
    }
    // mean over 256 entries (division by power of 2 is exact)
    g_active[idx] = (s * (1.0f / 256.0f) > 0.5f) ? 1.0f : 0.0f;
}

// ---------------------------------------------------------------------------
// Kernel 2: per-block 3x3 conv + bias + relu, gated.
// Grid: (4 f-groups, 256 blocks, 4 images). 256 threads.
// Thread tile: 2x2 px  x 16 f.  CTA computes 16x16 px region, writes 14x14.
// ---------------------------------------------------------------------------
__global__ void __launch_bounds__(256)
conv_kernel(const float* __restrict__ in, const float* __restrict__ ker,
            const float* __restrict__ bias, float* __restrict__ out) {
    // input patch: [c][row 0..17][col, pitch 20]  (c-major, 2-way conflicts max)
    __shared__ __align__(16) float s_in[CCH * 18 * 20];
    // weights: [tap 0..8][c 0..7][f 0..63]
    __shared__ __align__(16) float s_w[9 * CCH * FT];

    const int fg = blockIdx.x;          // 0..3
    const int bi = blockIdx.y >> 4;
    const int bj = blockIdx.y & 15;
    const int n  = blockIdx.z;

    const int tid = threadIdx.x;
    const int ft  = tid >> 6;           // 0..3  (16 f each)
    const int pt  = tid & 63;
    const int ty  = pt & 7;             // row group 0..7 (fast within warp)
    const int tx  = pt >> 3;            // col group 0..7
    const int oy  = 2 * ty;             // local output row base
    const int ox  = 2 * tx;
    const int f0  = fg * FT + ft * 16;  // this thread's 16 consecutive f

    const float act = g_active[n * 256 + blockIdx.y];

    if (act == 0.0f) {
        // inactive block: zero-fill the 14x14x64 output region
        for (int idx = tid; idx < OBS * OBS * (FT / 4); idx += 256) {
            int q = idx & 15;           // which float4 within 64 f
            int p = idx >> 4;           // pixel 0..195
            int hh = bi * OBS + p / OBS;
            int wc = bj * OBS + p % OBS;
            float4 z = make_float4(0.f, 0.f, 0.f, 0.f);
            *(float4*)&out[((n * HH + hh) * WW + wc) * FOUT + fg * FT + q * 4] = z;
        }
        return;
    }

    unsigned long long acc[4][8];       // 4 px x 8 f-pairs (16 f)
#pragma unroll
    for (int p = 0; p < 4; ++p)
#pragma unroll
        for (int q = 0; q < 8; ++q) acc[p][q] = 0ULL;

    const int ybase = bi * OBS - 1;     // global y of patch row 0
    const int xbase = bj * OBS - 1;

    for (int c0 = 0; c0 < CIN; c0 += CCH) {
        __syncthreads();
        // ---- stage input patch 18x18 x CCH (guarded, zero OOB) ----
        for (int idx = tid; idx < 18 * 18 * (CCH / 4); idx += 256) {
            int cc4 = idx & 1;          // 0 or 1 -> c offset 0 / 4
            int pos = idx >> 1;         // 0..323
            int r = pos / 18, col = pos % 18;
            int y = ybase + r, x = xbase + col;
            float4 v = make_float4(0.f, 0.f, 0.f, 0.f);
            if ((unsigned)y < (unsigned)HH && (unsigned)x < (unsigned)WW)
                v = *(const float4*)&in[((n * HH + y) * WW + x) * CIN + c0 + cc4 * 4];
            int base = (cc4 * 4) * 360 + r * 20 + col;
            s_in[base        ] = v.x;
            s_in[base +  360 ] = v.y;
            s_in[base +  720 ] = v.z;
            s_in[base + 1080 ] = v.w;
        }
        // ---- stage weights 9 taps x CCH x 64 ----
        for (int idx = tid; idx < 9 * CCH * (FT / 4); idx += 256) {
            int f4 = idx & 15;
            int rc = idx >> 4;          // tap*CCH + c
            int tap = rc / CCH, c = rc % CCH;
            float4 v = *(const float4*)&ker[(tap * CIN + c0 + c) * FOUT + fg * FT + f4 * 4];
            *(float4*)&s_w[rc * FT + f4 * 4] = v;
        }
        __syncthreads();

#pragma unroll 2
        for (int c = 0; c < CCH; ++c) {
            // 4x4 input window for this thread's 2x2 px / 3x3 taps, pre-packed
            unsigned long long a2[4][4];
#pragma unroll
            for (int r = 0; r < 4; ++r)
#pragma unroll
                for (int q = 0; q < 4; ++q) {
                    float av = s_in[c * 360 + (oy + r) * 20 + (ox + q)];
                    a2[r][q] = pack2(av, av);
                }
#pragma unroll
            for (int dy = 0; dy < 3; ++dy)
#pragma unroll
                for (int dx = 0; dx < 3; ++dx) {
                    const unsigned long long* wp = (const unsigned long long*)
                        &s_w[((dy * 3 + dx) * CCH + c) * FT + ft * 16];
                    unsigned long long w2[8];
#pragma unroll
                    for (int q = 0; q < 8; ++q) w2[q] = wp[q];
#pragma unroll
                    for (int i = 0; i < 2; ++i)
#pragma unroll
                        for (int j = 0; j < 2; ++j) {
                            unsigned long long av = a2[i + dy][j + dx];
#pragma unroll
                            for (int q = 0; q < 8; ++q)
                                fma2(acc[i * 2 + j][q], av, w2[q]);
                        }
                }
        }
    }

    // ---- epilogue: +bias, relu, write (only real 14x14 pixels) ----
    float bs[16];
#pragma unroll
    for (int q = 0; q < 4; ++q) {
        float4 b4 = *(const float4*)&bias[f0 + q * 4];
        bs[q * 4 + 0] = b4.x; bs[q * 4 + 1] = b4.y;
        bs[q * 4 + 2] = b4.z; bs[q * 4 + 3] = b4.w;
    }
#pragma unroll
    for (int i = 0; i < 2; ++i) {
        int yy = oy + i;
        if (yy >= OBS) continue;
#pragma unroll
        for (int j = 0; j < 2; ++j) {
            int xx = ox + j;
            if (xx >= OBS) continue;
            int p = i * 2 + j;
            float v[16];
#pragma unroll
            for (int q = 0; q < 8; ++q) {
                float2 t = unpack2(acc[p][q]);
                v[2 * q] = t.x; v[2 * q + 1] = t.y;
            }
            int o = ((n * HH + bi * OBS + yy) * WW + bj * OBS + xx) * FOUT + f0;
#pragma unroll
            for (int q = 0; q < 4; ++q) {
                float4 r4;
                r4.x = fmaxf(v[q * 4 + 0] + bs[q * 4 + 0], 0.f);
                r4.y = fmaxf(v[q * 4 + 1] + bs[q * 4 + 1], 0.f);
                r4.z = fmaxf(v[q * 4 + 2] + bs[q * 4 + 2], 0.f);
                r4.w = fmaxf(v[q * 4 + 3] + bs[q * 4 + 3], 0.f);
                *(float4*)&out[o + q * 4] = r4;
            }
        }
    }
}

// ---------------------------------------------------------------------------
extern "C" void kernel_launch(void* const* d_in, const int* in_sizes, int n_in,
                              void* d_out, int out_size) {
    const float* inputs = (const float*)d_in[0];   // (4,224,224,256)
    const float* mask   = (const float*)d_in[1];   // (4,224,224,1)
    const float* kernel = (const float*)d_in[2];   // (3,3,256,256)
    const float* bias   = (const float*)d_in[3];   // (256,)
    float* out = (float*)d_out;                    // (4,224,224,256)

    active_kernel<<<4, 256>>>(mask);

    dim3 grid(FOUT / FT, BC * BC, NB);             // (4, 256, 4)
    conv_kernel<<<grid, 256>>>(inputs, kernel, bias, out);
}

// round 5
// speedup vs baseline: 5.6133x; 5.6133x over previous
#include <cuda_runtime.h>
#include <cuda_fp16.h>
#include <stdint.h>

#define NB   4
#define HH   224
#define WW   224
#define CIN  256
#define FOUT 256
#define BCB  16
#define OBS  14
#define FT   64            // F per CTA
#define CCH  32            // channels per chunk
#define NCHUNK (CIN / CCH) // 8
#define THREADS 256

// smem: A patch 324 px * 64B = 20736 ; B double buffer 2 * 4096
#define SMEM_A 0
#define SMEM_B 20736
#define SMEM_SZ (20736 + 8192)

__device__ float  g_active[NB * BCB * BCB];
__device__ __half g_wf16[9 * 256 * 256];   // [tap][f][c]

static __device__ __forceinline__ uint32_t s2u(const void* p) {
    uint32_t a;
    asm("{ .reg .u64 t; cvta.to.shared.u64 t, %1; cvt.u32.u64 %0, t; }"
        : "=r"(a) : "l"(p));
    return a;
}
// pack {lo, hi} fp32 -> f16x2 (lo in low 16 bits)
static __device__ __forceinline__ uint32_t f2h2(float lo, float hi) {
    uint32_t r;
    asm("cvt.rn.f16x2.f32 %0, %1, %2;" : "=r"(r) : "f"(hi), "f"(lo));
    return r;
}
static __device__ __forceinline__ void ldsm4(uint32_t* r, uint32_t addr) {
    asm volatile("ldmatrix.sync.aligned.m8n8.x4.shared.b16 {%0,%1,%2,%3}, [%4];"
                 : "=r"(r[0]), "=r"(r[1]), "=r"(r[2]), "=r"(r[3]) : "r"(addr));
}
static __device__ __forceinline__ void mma16816(float* d, const uint32_t* a,
                                                uint32_t b0, uint32_t b1) {
    asm volatile(
        "mma.sync.aligned.m16n8k16.row.col.f32.f16.f16.f32 "
        "{%0,%1,%2,%3}, {%4,%5,%6,%7}, {%8,%9}, {%0,%1,%2,%3};"
        : "+f"(d[0]), "+f"(d[1]), "+f"(d[2]), "+f"(d[3])
        : "r"(a[0]), "r"(a[1]), "r"(a[2]), "r"(a[3]), "r"(b0), "r"(b1));
}

// ---------------------------------------------------------------------------
// Kernel 0: weights fp32 -> f16, layout [tap][f][c]
// ---------------------------------------------------------------------------
__global__ void wconv_kernel(const float* __restrict__ ker) {
    int idx = blockIdx.x * blockDim.x + threadIdx.x;
    if (idx >= 9 * 256 * 256) return;
    int c = idx & 255, f = (idx >> 8) & 255, tap = idx >> 16;
    g_wf16[idx] = __float2half_rn(ker[(tap * 256 + c) * 256 + f]);
}

// ---------------------------------------------------------------------------
// Kernel 1: block gates
// ---------------------------------------------------------------------------
__global__ void active_kernel(const float* __restrict__ mask) {
    int idx = blockIdx.x * blockDim.x + threadIdx.x;
    if (idx >= NB * BCB * BCB) return;
    int bj = idx & 15, bi = (idx >> 4) & 15, n = idx >> 8;
    int y0 = bi * OBS - 1, x0 = bj * OBS - 1;
    float s = 0.0f;
    for (int i = 0; i < 16; ++i) {
        int y = y0 + i;
        if ((unsigned)y >= (unsigned)HH) continue;
        const float* row = mask + (n * HH + y) * WW;
        for (int j = 0; j < 16; ++j) {
            int x = x0 + j;
            if ((unsigned)x < (unsigned)WW) s += row[x];
        }
    }
    g_active[idx] = (s * (1.0f / 256.0f) > 0.5f) ? 1.0f : 0.0f;
}

// ---------------------------------------------------------------------------
// Kernel 2: HMMA implicit-GEMM conv per active block.
// Grid (4 f-groups, 256 blocks, 4 images). 8 warps; warp owns 32 px rows.
// ---------------------------------------------------------------------------
__global__ void __launch_bounds__(THREADS, 2)
conv_mma(const float* __restrict__ in, const float* __restrict__ bias,
         float* __restrict__ out) {
    __shared__ __align__(128) char smem[SMEM_SZ];
    const uint32_t sA = s2u(smem) + SMEM_A;
    const uint32_t sB = s2u(smem) + SMEM_B;

    const int tid = threadIdx.x, wid = tid >> 5, lane = tid & 31;
    const int fg = blockIdx.x;
    const int bi = blockIdx.y >> 4, bj = blockIdx.y & 15;
    const int n = blockIdx.z;
    const int f0 = fg * FT;

    const float act = g_active[n * 256 + blockIdx.y];
    if (act == 0.0f) {
        float4 z = make_float4(0.f, 0.f, 0.f, 0.f);
        for (int idx = tid; idx < 196 * 16; idx += THREADS) {
            int q = idx & 15, p = idx >> 4;
            int hh = bi * OBS + p / OBS, wc = bj * OBS + p % OBS;
            *(float4*)&out[(((size_t)n * HH + hh) * WW + wc) * FOUT + f0 + q * 4] = z;
        }
        return;
    }

    const int ybase = bi * OBS - 1, xbase = bj * OBS - 1;
    const int warpM = wid * 32;

    float acc[2][8][4];
#pragma unroll
    for (int a = 0; a < 2; ++a)
#pragma unroll
        for (int b = 0; b < 8; ++b)
#pragma unroll
            for (int c = 0; c < 4; ++c) acc[a][b][c] = 0.0f;

    // ---- A patch staging: 324 px rows x 32 c f16 (64B), swizzled ----
    auto stageA = [&](int c0) {
#pragma unroll
        for (int it = 0; it < 6; ++it) {
            int i = tid + it * THREADS;
            if (i >= 324 * 4) break;
            int p = i >> 2, j = i & 3;
            int y = ybase + p / 18, x = xbase + p % 18;
            float4 v0 = make_float4(0.f, 0.f, 0.f, 0.f), v1 = v0;
            if ((unsigned)y < (unsigned)HH && (unsigned)x < (unsigned)WW) {
                const float* gp = in + ((((size_t)n * HH + y) * WW + x) << 8) + c0 + j * 8;
                v0 = *(const float4*)gp;
                v1 = *(const float4*)(gp + 4);
            }
            uint32_t h0 = f2h2(v0.x, v0.y);
            uint32_t h1 = f2h2(v0.z, v0.w);
            uint32_t h2 = f2h2(v1.x, v1.y);
            uint32_t h3 = f2h2(v1.z, v1.w);
            int jp = (j + (p >> 1)) & 3;
            *(uint4*)(smem + SMEM_A + p * 64 + 16 * jp) = make_uint4(h0, h1, h2, h3);
        }
    };

    // B prefetch (per-thread 16B): tap weights [64 f][32 c]
    auto loadB = [&](int T, uint4& wv) {
        int c0 = (T / 9) * CCH, tap = T % 9;
        int f = tid >> 2, j = tid & 3;
        wv = *(const uint4*)(g_wf16 + ((size_t)(tap * 256 + f0 + f) << 8) + c0 + j * 8);
    };
    auto storeB = [&](int T, const uint4& wv) {
        int f = tid >> 2, j = tid & 3;
        int jp = (j + ((f >> 1) & 3)) & 3;
        *(uint4*)(smem + SMEM_B + (T & 1) * 4096 + f * 64 + 16 * jp) = wv;
    };

    // prologue
    uint4 wv;
    loadB(0, wv);
    stageA(0);
    storeB(0, wv);
    __syncthreads();

    for (int T = 0; T < 72; ++T) {
        const int buf = T & 1;
        const int tap = T % 9;
        const int dy = tap / 3, dx = tap % 3;
        const bool hasNext = (T + 1 < 72);
        if (hasNext) loadB(T + 1, wv);

        // ---- A fragments: 2 m-tiles x 2 k-steps ----
        uint32_t afr[2][2][4];
#pragma unroll
        for (int mt = 0; mt < 2; ++mt) {
            int pm = warpM + mt * 16 + (lane & 15);
            int p = ((pm >> 4) + dy) * 18 + (pm & 15) + dx;
            uint32_t rowa = sA + p * 64;
            int psw = (p >> 1) & 3;
#pragma unroll
            for (int ks = 0; ks < 2; ++ks) {
                int j0 = ks * 2 + (lane >> 4);
                ldsm4(afr[mt][ks], rowa + 16 * ((j0 + psw) & 3));
            }
        }
        // ---- B fragments + mma, n16 group at a time ----
        const uint32_t bbase = sB + buf * 4096;
#pragma unroll
        for (int ng = 0; ng < 4; ++ng) {
            uint32_t bfr[2][4];
            int f = ng * 16 + (lane & 7) + ((lane >> 3) & 1) * 8;
            uint32_t rowb = bbase + f * 64;
            int fsw = (f >> 1) & 3;
#pragma unroll
            for (int ks = 0; ks < 2; ++ks) {
                int j0 = ks * 2 + (lane >> 4);
                ldsm4(bfr[ks], rowb + 16 * ((j0 + fsw) & 3));
            }
#pragma unroll
            for (int ks = 0; ks < 2; ++ks)
#pragma unroll
                for (int mt = 0; mt < 2; ++mt)
#pragma unroll
                    for (int nh = 0; nh < 2; ++nh)
                        mma16816(acc[mt][ng * 2 + nh], afr[mt][ks],
                                 bfr[ks][nh], bfr[ks][nh + 2]);
        }

        if (tap == 8 && hasNext) {
            __syncthreads();          // all warps done reading sA
            stageA(((T / 9) + 1) * CCH);
        }
        if (hasNext) storeB(T + 1, wv);
        __syncthreads();
    }

    // ---- epilogue: bias + relu + store ----
    float2 b2[8];
#pragma unroll
    for (int ng = 0; ng < 8; ++ng)
        b2[ng] = *(const float2*)&bias[f0 + ng * 8 + (lane & 3) * 2];

#pragma unroll
    for (int mt = 0; mt < 2; ++mt)
#pragma unroll
        for (int rr = 0; rr < 2; ++rr) {
            int m = warpM + mt * 16 + rr * 8 + (lane >> 2);
            int oy = m >> 4, ox = m & 15;
            if (oy >= OBS || ox >= OBS) continue;
            float* op = out + ((((size_t)n * HH + bi * OBS + oy) * WW) +
                               bj * OBS + ox) * FOUT + f0 + (lane & 3) * 2;
#pragma unroll
            for (int ng = 0; ng < 8; ++ng) {
                float2 v;
                v.x = fmaxf(acc[mt][ng][rr * 2 + 0] + b2[ng].x, 0.f);
                v.y = fmaxf(acc[mt][ng][rr * 2 + 1] + b2[ng].y, 0.f);
                *(float2*)(op + ng * 8) = v;
            }
        }
}

// ---------------------------------------------------------------------------
extern "C" void kernel_launch(void* const* d_in, const int* in_sizes, int n_in,
                              void* d_out, int out_size) {
    const float* inputs = (const float*)d_in[0];   // (4,224,224,256)
    const float* mask   = (const float*)d_in[1];   // (4,224,224,1)
    const float* kernel = (const float*)d_in[2];   // (3,3,256,256)
    const float* bias   = (const float*)d_in[3];   // (256,)
    float* out = (float*)d_out;

    wconv_kernel<<<(9 * 256 * 256 + 255) / 256, 256>>>(kernel);
    active_kernel<<<4, 256>>>(mask);

    dim3 grid(FOUT / FT, BCB * BCB, NB);           // (4, 256, 4)
    conv_mma<<<grid, THREADS>>>(inputs, bias, out);
}

// round 6
// speedup vs baseline: 5.7304x; 1.0209x over previous
#include <cuda_runtime.h>
#include <cuda_fp16.h>
#include <stdint.h>

#define NB   4
#define HH   224
#define WW   224
#define CIN  256
#define FOUT 256
#define BCB  16
#define OBS  14
#define FT   64            // F per CTA
#define CCH  32            // channels per chunk
#define NCHUNK (CIN / CCH) // 8
#define THREADS 256

// smem: A patch double buffer 2 * 324 px * 64B ; B double buffer 2 * 4096
#define ABUF   20736
#define SMEM_A 0
#define SMEM_B (2 * ABUF)          // 41472
#define SMEM_SZ (2 * ABUF + 8192)  // 49664

__device__ float  g_active[NB * BCB * BCB];
__device__ __half g_wf16[9 * 256 * 256];   // [tap][f][c]

static __device__ __forceinline__ uint32_t s2u(const void* p) {
    uint32_t a;
    asm("{ .reg .u64 t; cvta.to.shared.u64 t, %1; cvt.u32.u64 %0, t; }"
        : "=r"(a) : "l"(p));
    return a;
}
// pack {lo, hi} fp32 -> f16x2 (lo in low 16 bits)
static __device__ __forceinline__ uint32_t f2h2(float lo, float hi) {
    uint32_t r;
    asm("cvt.rn.f16x2.f32 %0, %1, %2;" : "=r"(r) : "f"(hi), "f"(lo));
    return r;
}
static __device__ __forceinline__ void ldsm4(uint32_t* r, uint32_t addr) {
    asm volatile("ldmatrix.sync.aligned.m8n8.x4.shared.b16 {%0,%1,%2,%3}, [%4];"
                 : "=r"(r[0]), "=r"(r[1]), "=r"(r[2]), "=r"(r[3]) : "r"(addr));
}
static __device__ __forceinline__ void mma16816(float* d, const uint32_t* a,
                                                uint32_t b0, uint32_t b1) {
    asm volatile(
        "mma.sync.aligned.m16n8k16.row.col.f32.f16.f16.f32 "
        "{%0,%1,%2,%3}, {%4,%5,%6,%7}, {%8,%9}, {%0,%1,%2,%3};"
        : "+f"(d[0]), "+f"(d[1]), "+f"(d[2]), "+f"(d[3])
        : "r"(a[0]), "r"(a[1]), "r"(a[2]), "r"(a[3]), "r"(b0), "r"(b1));
}

// ---------------------------------------------------------------------------
// Kernel 0: weights fp32 -> f16, layout [tap][f][c]
// ---------------------------------------------------------------------------
__global__ void wconv_kernel(const float* __restrict__ ker) {
    int idx = blockIdx.x * blockDim.x + threadIdx.x;
    if (idx >= 9 * 256 * 256) return;
    int c = idx & 255, f = (idx >> 8) & 255, tap = idx >> 16;
    g_wf16[idx] = __float2half_rn(ker[(tap * 256 + c) * 256 + f]);
}

// ---------------------------------------------------------------------------
// Kernel 1: block gates
// ---------------------------------------------------------------------------
__global__ void active_kernel(const float* __restrict__ mask) {
    int idx = blockIdx.x * blockDim.x + threadIdx.x;
    if (idx >= NB * BCB * BCB) return;
    int bj = idx & 15, bi = (idx >> 4) & 15, n = idx >> 8;
    int y0 = bi * OBS - 1, x0 = bj * OBS - 1;
    float s = 0.0f;
    for (int i = 0; i < 16; ++i) {
        int y = y0 + i;
        if ((unsigned)y >= (unsigned)HH) continue;
        const float* row = mask + (n * HH + y) * WW;
        for (int j = 0; j < 16; ++j) {
            int x = x0 + j;
            if ((unsigned)x < (unsigned)WW) s += row[x];
        }
    }
    g_active[idx] = (s * (1.0f / 256.0f) > 0.5f) ? 1.0f : 0.0f;
}

// ---------------------------------------------------------------------------
// Kernel 2: HMMA implicit-GEMM conv per active block.
// Grid (4 f-groups, 256 blocks, 4 images). 8 warps; warp owns 32 px rows.
// A patch double-buffered; next-chunk staging spread across the 9 taps.
// ---------------------------------------------------------------------------
__global__ void __launch_bounds__(THREADS, 2)
conv_mma(const float* __restrict__ in, const float* __restrict__ bias,
         float* __restrict__ out) {
    __shared__ __align__(128) char smem[SMEM_SZ];
    const uint32_t sA = s2u(smem) + SMEM_A;
    const uint32_t sB = s2u(smem) + SMEM_B;

    const int tid = threadIdx.x, wid = tid >> 5, lane = tid & 31;
    const int fg = blockIdx.x;
    const int bi = blockIdx.y >> 4, bj = blockIdx.y & 15;
    const int n = blockIdx.z;
    const int f0 = fg * FT;

    const float act = g_active[n * 256 + blockIdx.y];
    if (act == 0.0f) {
        float4 z = make_float4(0.f, 0.f, 0.f, 0.f);
        for (int idx = tid; idx < 196 * 16; idx += THREADS) {
            int q = idx & 15, p = idx >> 4;
            int hh = bi * OBS + p / OBS, wc = bj * OBS + p % OBS;
            *(float4*)&out[(((size_t)n * HH + hh) * WW + wc) * FOUT + f0 + q * 4] = z;
        }
        return;
    }

    const int ybase = bi * OBS - 1, xbase = bj * OBS - 1;
    const int warpM = wid * 32;

    float acc[2][8][4];
#pragma unroll
    for (int a = 0; a < 2; ++a)
#pragma unroll
        for (int b = 0; b < 8; ++b)
#pragma unroll
            for (int c = 0; c < 4; ++c) acc[a][b][c] = 0.0f;

    // ---- full A staging (prologue only): 324 px x 32c f16, swizzled ----
    auto stageA = [&](int c0, int abuf) {
#pragma unroll
        for (int it = 0; it < 6; ++it) {
            int i = tid + it * THREADS;
            if (i >= 324 * 4) break;
            int p = i >> 2, j = i & 3;
            int y = ybase + p / 18, x = xbase + p % 18;
            float4 v0 = make_float4(0.f, 0.f, 0.f, 0.f), v1 = v0;
            if ((unsigned)y < (unsigned)HH && (unsigned)x < (unsigned)WW) {
                const float* gp = in + ((((size_t)n * HH + y) * WW + x) << 8) + c0 + j * 8;
                v0 = *(const float4*)gp;
                v1 = *(const float4*)(gp + 4);
            }
            int jp = (j + (p >> 1)) & 3;
            *(uint4*)(smem + SMEM_A + abuf * ABUF + p * 64 + 16 * jp) =
                make_uint4(f2h2(v0.x, v0.y), f2h2(v0.z, v0.w),
                           f2h2(v1.x, v1.y), f2h2(v1.z, v1.w));
        }
    };

    // B prefetch (per-thread 16B): tap weights [64 f][32 c]
    auto loadB = [&](int c0, int tap, uint4& wv) {
        int f = tid >> 2, j = tid & 3;
        wv = *(const uint4*)(g_wf16 + ((size_t)(tap * 256 + f0 + f) << 8) + c0 + j * 8);
    };
    auto storeB = [&](int buf, const uint4& wv) {
        int f = tid >> 2, j = tid & 3;
        int jp = (j + ((f >> 1) & 3)) & 3;
        *(uint4*)(smem + SMEM_B + buf * 4096 + f * 64 + 16 * jp) = wv;
    };

    // prologue
    uint4 wv;
    loadB(0, 0, wv);
    stageA(0, 0);
    storeB(0, wv);
    __syncthreads();

    const bool sliceT = (tid < 144);
    int tap = 0, kc = 0;
    for (int T = 0; T < 72; ++T) {
        const int buf = T & 1;
        const int dy = tap / 3, dx = tap % 3;   // tap in [0,8]: cheap
        const bool hasNext = (T + 1 < 72);
        const bool doSlice = (kc < NCHUNK - 1) && sliceT;

        // ---- issue next-chunk A slice LDG early (latency hides behind MMA) ----
        float4 v0, v1;
        int sp = 0, sj = 0;
        if (doSlice) {
            int i = tap * 144 + tid;            // 0..1295 over the 9 taps
            sp = i >> 2; sj = i & 3;
            int y = ybase + sp / 18, x = xbase + sp % 18;
            v0 = make_float4(0.f, 0.f, 0.f, 0.f); v1 = v0;
            if ((unsigned)y < (unsigned)HH && (unsigned)x < (unsigned)WW) {
                const float* gp = in + ((((size_t)n * HH + y) * WW + x) << 8) +
                                  (kc + 1) * CCH + sj * 8;
                v0 = *(const float4*)gp;
                v1 = *(const float4*)(gp + 4);
            }
        }
        if (hasNext) {
            int nt = tap + 1, nk = kc;
            if (nt == 9) { nt = 0; ++nk; }
            loadB(nk * CCH, nt, wv);
        }

        // ---- A fragments: 2 m-tiles x 2 k-steps, from buffer kc&1 ----
        const uint32_t aB = sA + (uint32_t)(kc & 1) * ABUF;
        uint32_t afr[2][2][4];
#pragma unroll
        for (int mt = 0; mt < 2; ++mt) {
            int pm = warpM + mt * 16 + (lane & 15);
            int p = ((pm >> 4) + dy) * 18 + (pm & 15) + dx;
            uint32_t rowa = aB + p * 64;
            int psw = (p >> 1) & 3;
#pragma unroll
            for (int ks = 0; ks < 2; ++ks) {
                int j0 = ks * 2 + (lane >> 4);
                ldsm4(afr[mt][ks], rowa + 16 * ((j0 + psw) & 3));
            }
        }
        // ---- B fragments + mma, n16 group at a time ----
        const uint32_t bbase = sB + buf * 4096;
#pragma unroll
        for (int ng = 0; ng < 4; ++ng) {
            uint32_t bfr[2][4];
            int f = ng * 16 + (lane & 7) + ((lane >> 3) & 1) * 8;
            uint32_t rowb = bbase + f * 64;
            int fsw = (f >> 1) & 3;
#pragma unroll
            for (int ks = 0; ks < 2; ++ks) {
                int j0 = ks * 2 + (lane >> 4);
                ldsm4(bfr[ks], rowb + 16 * ((j0 + fsw) & 3));
            }
#pragma unroll
            for (int ks = 0; ks < 2; ++ks)
#pragma unroll
                for (int mt = 0; mt < 2; ++mt)
#pragma unroll
                    for (int nh = 0; nh < 2; ++nh)
                        mma16816(acc[mt][ng * 2 + nh], afr[mt][ks],
                                 bfr[ks][nh], bfr[ks][nh + 2]);
        }

        // ---- land next-chunk A slice + next B tile, then publish ----
        if (doSlice) {
            int jp = (sj + (sp >> 1)) & 3;
            *(uint4*)(smem + SMEM_A + ((kc + 1) & 1) * ABUF + sp * 64 + 16 * jp) =
                make_uint4(f2h2(v0.x, v0.y), f2h2(v0.z, v0.w),
                           f2h2(v1.x, v1.y), f2h2(v1.z, v1.w));
        }
        if (hasNext) storeB(buf ^ 1, wv);
        __syncthreads();

        if (++tap == 9) { tap = 0; ++kc; }
    }

    // ---- epilogue: bias + relu + store ----
    float2 b2[8];
#pragma unroll
    for (int ng = 0; ng < 8; ++ng)
        b2[ng] = *(const float2*)&bias[f0 + ng * 8 + (lane & 3) * 2];

#pragma unroll
    for (int mt = 0; mt < 2; ++mt)
#pragma unroll
        for (int rr = 0; rr < 2; ++rr) {
            int m = warpM + mt * 16 + rr * 8 + (lane >> 2);
            int oy = m >> 4, ox = m & 15;
            if (oy >= OBS || ox >= OBS) continue;
            float* op = out + ((((size_t)n * HH + bi * OBS + oy) * WW) +
                               bj * OBS + ox) * FOUT + f0 + (lane & 3) * 2;
#pragma unroll
            for (int ng = 0; ng < 8; ++ng) {
                float2 v;
                v.x = fmaxf(acc[mt][ng][rr * 2 + 0] + b2[ng].x, 0.f);
                v.y = fmaxf(acc[mt][ng][rr * 2 + 1] + b2[ng].y, 0.f);
                *(float2*)(op + ng * 8) = v;
            }
        }
}

// ---------------------------------------------------------------------------
extern "C" void kernel_launch(void* const* d_in, const int* in_sizes, int n_in,
                              void* d_out, int out_size) {
    const float* inputs = (const float*)d_in[0];   // (4,224,224,256)
    const float* mask   = (const float*)d_in[1];   // (4,224,224,1)
    const float* kernel = (const float*)d_in[2];   // (3,3,256,256)
    const float* bias   = (const float*)d_in[3];   // (256,)
    float* out = (float*)d_out;

    wconv_kernel<<<(9 * 256 * 256 + 255) / 256, 256>>>(kernel);
    active_kernel<<<4, 256>>>(mask);

    dim3 grid(FOUT / FT, BCB * BCB, NB);           // (4, 256, 4)
    conv_mma<<<grid, THREADS>>>(inputs, bias, out);
}

// round 7
// speedup vs baseline: 6.4671x; 1.1286x over previous
#include <cuda_runtime.h>
#include <cuda_fp16.h>
#include <stdint.h>

#define NB   4
#define HH   224
#define WW   224
#define CIN  256
#define FOUT 256
#define BCB  16
#define OBS  14
#define FT   64            // F per CTA
#define CCH  32            // channels per chunk
#define NCHUNK (CIN / CCH) // 8
#define THREADS 256

// dynamic smem: A double buffer 2*20736 ; B(3 taps) double buffer 2*12288
#define ABUF    20736
#define SMEM_B  (2 * ABUF)           // 41472
#define BBUF    12288
#define SMEM_SZ (2 * ABUF + 2 * BBUF) // 66048

__device__ float  g_active[NB * BCB * BCB];
__device__ __half g_wf16[9 * 256 * 256];   // [tap][f][c]

static __device__ __forceinline__ uint32_t s2u(const void* p) {
    uint32_t a;
    asm("{ .reg .u64 t; cvta.to.shared.u64 t, %1; cvt.u32.u64 %0, t; }"
        : "=r"(a) : "l"(p));
    return a;
}
static __device__ __forceinline__ uint32_t f2h2(float lo, float hi) {
    uint32_t r;
    asm("cvt.rn.f16x2.f32 %0, %1, %2;" : "=r"(r) : "f"(hi), "f"(lo));
    return r;
}
static __device__ __forceinline__ void ldsm4(uint32_t* r, uint32_t addr) {
    asm volatile("ldmatrix.sync.aligned.m8n8.x4.shared.b16 {%0,%1,%2,%3}, [%4];"
                 : "=r"(r[0]), "=r"(r[1]), "=r"(r[2]), "=r"(r[3]) : "r"(addr));
}
static __device__ __forceinline__ void mma16816(float* d, const uint32_t* a,
                                                uint32_t b0, uint32_t b1) {
    asm volatile(
        "mma.sync.aligned.m16n8k16.row.col.f32.f16.f16.f32 "
        "{%0,%1,%2,%3}, {%4,%5,%6,%7}, {%8,%9}, {%0,%1,%2,%3};"
        : "+f"(d[0]), "+f"(d[1]), "+f"(d[2]), "+f"(d[3])
        : "r"(a[0]), "r"(a[1]), "r"(a[2]), "r"(a[3]), "r"(b0), "r"(b1));
}

// ---------------------------------------------------------------------------
// Kernel 0 (fused prep): blocks 0..2303 convert weights; 2304..2307 gates
// ---------------------------------------------------------------------------
__global__ void prep_kernel(const float* __restrict__ ker,
                            const float* __restrict__ mask) {
    int b = blockIdx.x, tid = threadIdx.x;
    if (b < 2304) {
        int idx = b * 256 + tid;
        int c = idx & 255, f = (idx >> 8) & 255, tap = idx >> 16;
        g_wf16[idx] = __float2half_rn(ker[(tap * 256 + c) * 256 + f]);
    } else {
        int idx = (b - 2304) * 256 + tid;      // 0..1023
        int bj = idx & 15, bi = (idx >> 4) & 15, n = idx >> 8;
        int y0 = bi * OBS - 1, x0 = bj * OBS - 1;
        float s = 0.0f;
        for (int i = 0; i < 16; ++i) {
            int y = y0 + i;
            if ((unsigned)y >= (unsigned)HH) continue;
            const float* row = mask + (n * HH + y) * WW;
            for (int j = 0; j < 16; ++j) {
                int x = x0 + j;
                if ((unsigned)x < (unsigned)WW) s += row[x];
            }
        }
        g_active[idx] = (s * (1.0f / 256.0f) > 0.5f) ? 1.0f : 0.0f;
    }
}

// ---------------------------------------------------------------------------
// Kernel 1: HMMA implicit-GEMM conv. Grid (4 fg, 256 blocks, 4 images).
// 8 warps; warp owns 32 px rows (M=256 total), N=64, K=2304.
// Loop: 24 groups (8 c-chunks x 3 dx); per group 3 dy-taps share A frags.
// ---------------------------------------------------------------------------
__global__ void __launch_bounds__(THREADS, 2)
conv_mma(const float* __restrict__ in, const float* __restrict__ bias,
         float* __restrict__ out) {
    extern __shared__ char smem[];
    const uint32_t sA = s2u(smem);
    const uint32_t sB = sA + SMEM_B;

    const int tid = threadIdx.x, wid = tid >> 5, lane = tid & 31;
    const int fg = blockIdx.x;
    const int bi = blockIdx.y >> 4, bj = blockIdx.y & 15;
    const int n = blockIdx.z;
    const int f0 = fg * FT;

    const float act = g_active[n * 256 + blockIdx.y];
    if (act == 0.0f) {
        float4 z = make_float4(0.f, 0.f, 0.f, 0.f);
        for (int idx = tid; idx < 196 * 16; idx += THREADS) {
            int q = idx & 15, p = idx >> 4;
            int hh = bi * OBS + p / OBS, wc = bj * OBS + p % OBS;
            *(float4*)&out[(((size_t)n * HH + hh) * WW + wc) * FOUT + f0 + q * 4] = z;
        }
        return;
    }

    const int ybase = bi * OBS - 1, xbase = bj * OBS - 1;

    float acc[2][8][4];
#pragma unroll
    for (int a = 0; a < 2; ++a)
#pragma unroll
        for (int b = 0; b < 8; ++b)
#pragma unroll
            for (int c = 0; c < 4; ++c) acc[a][b][c] = 0.0f;

    // ---- full A staging (prologue): 324 px x 32c f16, swizzled ----
    auto stageA = [&](int c0, int abuf) {
#pragma unroll
        for (int it = 0; it < 6; ++it) {
            int i = tid + it * THREADS;
            if (i >= 324 * 4) break;
            int p = i >> 2, j = i & 3;
            int y = ybase + p / 18, x = xbase + p % 18;
            float4 v0 = make_float4(0.f, 0.f, 0.f, 0.f), v1 = v0;
            if ((unsigned)y < (unsigned)HH && (unsigned)x < (unsigned)WW) {
                const float* gp = in + ((((size_t)n * HH + y) * WW + x) << 8) + c0 + j * 8;
                v0 = *(const float4*)gp;
                v1 = *(const float4*)(gp + 4);
            }
            int jp = (j + (p >> 1)) & 3;
            *(uint4*)(smem + abuf * ABUF + p * 64 + 16 * jp) =
                make_uint4(f2h2(v0.x, v0.y), f2h2(v0.z, v0.w),
                           f2h2(v1.x, v1.y), f2h2(v1.z, v1.w));
        }
    };

    // B prefetch: 3 taps (dy=0..2 at fixed dx) x [64 f][32 c]
    const int bf = tid >> 2, bjj = tid & 3;
    const int bjp = (bjj + ((bf >> 1) & 3)) & 3;
    auto loadB3 = [&](int kcn, int dxn, uint4* wv) {
#pragma unroll
        for (int dy = 0; dy < 3; ++dy) {
            int tap = dy * 3 + dxn;
            wv[dy] = *(const uint4*)(g_wf16 + ((size_t)(tap * 256 + f0 + bf) << 8) +
                                     kcn * CCH + bjj * 8);
        }
    };
    auto storeB3 = [&](int buf, const uint4* wv) {
#pragma unroll
        for (int dy = 0; dy < 3; ++dy)
            *(uint4*)(smem + SMEM_B + buf * BBUF + dy * 4096 + bf * 64 + 16 * bjp) = wv[dy];
    };

    // prologue
    uint4 wv[3];
    loadB3(0, 0, wv);
    stageA(0, 0);
    storeB3(0, wv);
    __syncthreads();

    const bool hasItemB = (tid < 176);
    int dx = 0, kc = 0;
    for (int G = 0; G < 24; ++G) {
        const bool hasNext = (G < 23);
        if (hasNext) {
            int dxn = dx + 1, kcn = kc;
            if (dxn == 3) { dxn = 0; ++kcn; }
            loadB3(kcn, dxn, wv);
        }
        // ---- next-chunk A slice LDGs (1296 items over the 3 groups) ----
        const bool doSlice = (kc < NCHUNK - 1);
        float4 va0, va1, vb0, vb1;
        int spA = 0, sjA = 0, spB = 0, sjB = 0;
        if (doSlice) {
            int i = dx * 432 + tid;
            spA = i >> 2; sjA = i & 3;
            int y = ybase + spA / 18, x = xbase + spA % 18;
            va0 = make_float4(0.f, 0.f, 0.f, 0.f); va1 = va0;
            if ((unsigned)y < (unsigned)HH && (unsigned)x < (unsigned)WW) {
                const float* gp = in + ((((size_t)n * HH + y) * WW + x) << 8) +
                                  (kc + 1) * CCH + sjA * 8;
                va0 = *(const float4*)gp; va1 = *(const float4*)(gp + 4);
            }
            if (hasItemB) {
                int i2 = dx * 432 + 256 + tid;
                spB = i2 >> 2; sjB = i2 & 3;
                int y2 = ybase + spB / 18, x2 = xbase + spB % 18;
                vb0 = make_float4(0.f, 0.f, 0.f, 0.f); vb1 = vb0;
                if ((unsigned)y2 < (unsigned)HH && (unsigned)x2 < (unsigned)WW) {
                    const float* gp = in + ((((size_t)n * HH + y2) * WW + x2) << 8) +
                                      (kc + 1) * CCH + sjB * 8;
                    vb0 = *(const float4*)gp; vb1 = *(const float4*)(gp + 4);
                }
            }
        }

        const uint32_t aB = sA + (uint32_t)(kc & 1) * ABUF;
        const uint32_t bbuf = sB + (uint32_t)(G & 1) * BBUF;
#pragma unroll
        for (int ks = 0; ks < 2; ++ks) {
            const int j0 = ks * 2 + (lane >> 4);
            uint32_t afr[4][4];
#pragma unroll
            for (int pg = 0; pg < 4; ++pg) {
                int p = (wid * 2 + pg) * 18 + (lane & 15) + dx;
                uint32_t rowa = aB + p * 64;
                int psw = (p >> 1) & 3;
                ldsm4(afr[pg], rowa + 16 * ((j0 + psw) & 3));
            }
#pragma unroll
            for (int dy = 0; dy < 3; ++dy) {
#pragma unroll
                for (int ng = 0; ng < 4; ++ng) {
                    uint32_t bfr[4];
                    int f = ng * 16 + (lane & 7) + ((lane >> 3) & 1) * 8;
                    uint32_t rowb = bbuf + dy * 4096 + f * 64;
                    int fsw = (f >> 1) & 3;
                    ldsm4(bfr, rowb + 16 * ((j0 + fsw) & 3));
#pragma unroll
                    for (int mt = 0; mt < 2; ++mt)
#pragma unroll
                        for (int nh = 0; nh < 2; ++nh)
                            mma16816(acc[mt][ng * 2 + nh], afr[mt + dy],
                                     bfr[nh], bfr[nh + 2]);
                }
            }
        }

        // ---- land slices + next B, publish ----
        if (doSlice) {
            int jp = (sjA + (spA >> 1)) & 3;
            *(uint4*)(smem + ((kc + 1) & 1) * ABUF + spA * 64 + 16 * jp) =
                make_uint4(f2h2(va0.x, va0.y), f2h2(va0.z, va0.w),
                           f2h2(va1.x, va1.y), f2h2(va1.z, va1.w));
            if (hasItemB) {
                int jp2 = (sjB + (spB >> 1)) & 3;
                *(uint4*)(smem + ((kc + 1) & 1) * ABUF + spB * 64 + 16 * jp2) =
                    make_uint4(f2h2(vb0.x, vb0.y), f2h2(vb0.z, vb0.w),
                               f2h2(vb1.x, vb1.y), f2h2(vb1.z, vb1.w));
            }
        }
        if (hasNext) storeB3((G + 1) & 1, wv);
        __syncthreads();

        if (++dx == 3) { dx = 0; ++kc; }
    }

    // ---- epilogue: bias + relu + store ----
    const int warpM = wid * 32;
    float2 b2[8];
#pragma unroll
    for (int ng = 0; ng < 8; ++ng)
        b2[ng] = *(const float2*)&bias[f0 + ng * 8 + (lane & 3) * 2];

#pragma unroll
    for (int mt = 0; mt < 2; ++mt)
#pragma unroll
        for (int rr = 0; rr < 2; ++rr) {
            int m = warpM + mt * 16 + rr * 8 + (lane >> 2);
            int oy = m >> 4, ox = m & 15;
            if (oy >= OBS || ox >= OBS) continue;
            float* op = out + ((((size_t)n * HH + bi * OBS + oy) * WW) +
                               bj * OBS + ox) * FOUT + f0 + (lane & 3) * 2;
#pragma unroll
            for (int ng = 0; ng < 8; ++ng) {
                float2 v;
                v.x = fmaxf(acc[mt][ng][rr * 2 + 0] + b2[ng].x, 0.f);
                v.y = fmaxf(acc[mt][ng][rr * 2 + 1] + b2[ng].y, 0.f);
                *(float2*)(op + ng * 8) = v;
            }
        }
}

// ---------------------------------------------------------------------------
extern "C" void kernel_launch(void* const* d_in, const int* in_sizes, int n_in,
                              void* d_out, int out_size) {
    const float* inputs = (const float*)d_in[0];   // (4,224,224,256)
    const float* mask   = (const float*)d_in[1];   // (4,224,224,1)
    const float* kernel = (const float*)d_in[2];   // (3,3,256,256)
    const float* bias   = (const float*)d_in[3];   // (256,)
    float* out = (float*)d_out;

    static int configured = 0;
    if (!configured) {
        cudaFuncSetAttribute(conv_mma, cudaFuncAttributeMaxDynamicSharedMemorySize,
                             SMEM_SZ);
        configured = 1;
    }

    prep_kernel<<<2308, 256>>>(kernel, mask);

    dim3 grid(FOUT / FT, BCB * BCB, NB);           // (4, 256, 4)
    conv_mma<<<grid, THREADS, SMEM_SZ>>>(inputs, bias, out);
}